// round 11
// baseline (speedup 1.0000x reference)
#include <cuda_runtime.h>
#include <cstdint>
#include <cstddef>

// Problem constants (fixed by the reference)
#define NN    50000
#define HH    128
#define TT    4
#define EE    150000
#define K4    512      // T*H
#define SEGS  (NN*TT)

// ---------------------------------------------------------------------------
// Scratch (no allocations allowed -> __device__ globals)
// ---------------------------------------------------------------------------
__device__ __align__(16) float g_h    [(size_t)NN * HH];   // full-precision hidden
__device__ __align__(16) float g_h32  [(size_t)NN * HH];   // tf32-rounded copy of h
__device__ __align__(16) float g_S    [(size_t)NN * K4];   // rounded typed sums
__device__ __align__(16) float g_inc  [(size_t)NN * HH];   // rounded messages
__device__ __align__(16) float g_gates[(size_t)NN * 384];  // r|z|xn pre-activations
__device__ __align__(16) float g_gc1  [(size_t)NN * 384];  // layer1 const x-part
__device__ __align__(16) float g_Wcat [2 * HH * K4];       // rounded
__device__ __align__(16) float g_Wrz0 [256 * 256];         // rounded
__device__ __align__(16) float g_Wrz1 [256 * 256];         // rounded
__device__ __align__(16) float g_W1x  [384 * 128];         // rounded
__device__ __align__(16) float g_Wxn0 [128 * 128];         // rounded
__device__ __align__(16) float g_Wxn1 [128 * 128];         // rounded
__device__ __align__(16) float g_Whn0 [128 * 128];         // rounded
__device__ __align__(16) float g_Whn1 [128 * 128];         // rounded
__device__ float g_b0cat[384];
__device__ float g_b1cat[384];
__device__ int   g_cnt  [SEGS];
__device__ int   g_off  [SEGS + 1];
__device__ int   g_cur  [SEGS];
__device__ int   g_csr  [TT * EE];

// ---------------------------------------------------------------------------
// tf32 helpers
// ---------------------------------------------------------------------------
__device__ __forceinline__ float to_tf32(float x)
{
    uint32_t u;
    asm("cvt.rna.tf32.f32 %0, %1;" : "=r"(u) : "f"(x));
    return __uint_as_float(u);
}

__device__ __forceinline__ void mma_tf32(float* c, const uint32_t* a, const uint32_t* b)
{
    asm volatile(
        "mma.sync.aligned.m16n8k8.row.col.f32.tf32.tf32.f32 "
        "{%0,%1,%2,%3}, {%4,%5,%6,%7}, {%8,%9}, {%0,%1,%2,%3};"
        : "+f"(c[0]), "+f"(c[1]), "+f"(c[2]), "+f"(c[3])
        : "r"(a[0]), "r"(a[1]), "r"(a[2]), "r"(a[3]),
          "r"(b[0]), "r"(b[1]));
}

__device__ __forceinline__ void ldsm_x4(uint32_t* r, uint32_t addr)
{
    asm volatile(
        "ldmatrix.sync.aligned.m8n8.x4.shared.b16 {%0,%1,%2,%3}, [%4];"
        : "=r"(r[0]), "=r"(r[1]), "=r"(r[2]), "=r"(r[3]) : "r"(addr));
}

#define CP_COMMIT() asm volatile("cp.async.commit_group;\n" ::: "memory")
#define CP_WAIT0()  asm volatile("cp.async.wait_group 0;\n" ::: "memory")
#define CP_WAIT1()  asm volatile("cp.async.wait_group 1;\n" ::: "memory")

// ---------------------------------------------------------------------------
// wcat + zero(cnt): rearrange/round msg_W AND zero the CSR counters.
// Launched first so the capture slot lands on agg_kernel later.
// ---------------------------------------------------------------------------
__global__ void wcat_zero_kernel(const float* __restrict__ msg_W)
{
    int idx = blockIdx.x * blockDim.x + threadIdx.x;
    if (idx < 2 * HH * K4) {
        int l  = idx / (HH * K4);
        int r  = idx % (HH * K4);
        int f  = r / K4;
        int kk = r % K4;
        int t  = kk >> 7;
        int k  = kk & 127;
        g_Wcat[idx] = to_tf32(msg_W[(((size_t)l * TT + t) * HH + f) * HH + k]);
    }
    if (idx < SEGS) g_cnt[idx] = 0;
}

// ---------------------------------------------------------------------------
// CSR build (edges identical across timesteps -> once per launch)
// ---------------------------------------------------------------------------
__global__ void count_kernel(const int* __restrict__ edges)
{
    int idx = blockIdx.x * blockDim.x + threadIdx.x;
    if (idx >= TT * EE) return;
    int t   = idx / EE;
    int tgt = edges[(size_t)idx * 2 + 1];
    atomicAdd(&g_cnt[tgt * TT + t], 1);
}

__global__ void scan_kernel()
{
    __shared__ int s[1024];
    const int n     = SEGS;
    const int chunk = (n + 1023) / 1024;
    int tid = threadIdx.x;
    int lo  = tid * chunk;
    int hi  = min(lo + chunk, n);

    int sum = 0;
    for (int i = lo; i < hi; ++i) sum += g_cnt[i];
    s[tid] = sum;
    __syncthreads();
    for (int o = 1; o < 1024; o <<= 1) {
        int v = (tid >= o) ? s[tid - o] : 0;
        __syncthreads();
        s[tid] += v;
        __syncthreads();
    }
    int run = (tid == 0) ? 0 : s[tid - 1];
    for (int i = lo; i < hi; ++i) { g_off[i] = run; run += g_cnt[i]; }
    if (tid == 1023) g_off[n] = s[1023];
}

__global__ void fill_kernel(const int* __restrict__ edges)
{
    int idx = blockIdx.x * blockDim.x + threadIdx.x;
    if (idx >= TT * EE) return;
    int t   = idx / EE;
    int src = edges[(size_t)idx * 2 + 0];
    int tgt = edges[(size_t)idx * 2 + 1];
    int seg = tgt * TT + t;
    int pos = atomicAdd(&g_cur[seg], 1);
    g_csr[pos] = src;
}

// ---------------------------------------------------------------------------
// Build all rounded gate weights + biases
// ---------------------------------------------------------------------------
__global__ void build_prep(const float* __restrict__ W0i, const float* __restrict__ W0h,
                           const float* __restrict__ b0i, const float* __restrict__ b0h,
                           const float* __restrict__ W1i, const float* __restrict__ W1h,
                           const float* __restrict__ b1i, const float* __restrict__ b1h)
{
    int idx = blockIdx.x * blockDim.x + threadIdx.x;
    if (idx < 65536) {
        int j = idx >> 8, k = idx & 255;
        float v = (k < 128) ? W0i[j * 128 + k] : W0h[j * 128 + (k - 128)];
        g_Wrz0[idx] = to_tf32(v);
    } else if (idx < 131072) {
        int r = idx - 65536;
        int j = r >> 8, k = r & 255;
        float v = (k < 128) ? W1i[j * 256 + 128 + k] : W1h[j * 128 + (k - 128)];
        g_Wrz1[r] = to_tf32(v);
    } else if (idx < 180224) {                   // W1x [384][128]
        int r = idx - 131072;
        int j = r >> 7, k = r & 127;
        g_W1x[r] = to_tf32(W1i[j * 256 + k]);
    } else if (idx < 196608) {                   // Wxn0 [128][128]
        int r = idx - 180224;
        int j = r >> 7, k = r & 127;
        g_Wxn0[r] = to_tf32(W0i[(256 + j) * 128 + k]);
    } else if (idx < 212992) {                   // Wxn1
        int r = idx - 196608;
        int j = r >> 7, k = r & 127;
        g_Wxn1[r] = to_tf32(W1i[(256 + j) * 256 + 128 + k]);
    } else if (idx < 229376) {                   // Whn0
        int r = idx - 212992;
        int j = r >> 7, k = r & 127;
        g_Whn0[r] = to_tf32(W0h[(256 + j) * 128 + k]);
    } else if (idx < 245760) {                   // Whn1
        int r = idx - 229376;
        int j = r >> 7, k = r & 127;
        g_Whn1[r] = to_tf32(W1h[(256 + j) * 128 + k]);
    } else if (idx < 246144) {                   // b0cat
        int j = idx - 245760;
        g_b0cat[j] = (j < 256) ? (b0i[j] + b0h[j]) : b0i[j];
    } else if (idx < 246528) {                   // b1cat
        int j = idx - 246144;
        g_b1cat[j] = (j < 256) ? (b1i[j] + b1h[j]) : b1i[j];
    }
}

// h32 = tf32(x)
__global__ void round_kernel(const float* __restrict__ x, float* __restrict__ y)
{
    int idx = blockIdx.x * blockDim.x + threadIdx.x;
    if (idx < NN * HH) y[idx] = to_tf32(x[idx]);
}

// ---------------------------------------------------------------------------
// Aggregation: one fused loop over the node's whole edge range; 4 register
// accumulators selected by segment boundary (uniform per-warp branches).
// Per-type accumulation order identical to the serial version.
// ---------------------------------------------------------------------------
__global__ void __launch_bounds__(128)
agg_kernel(const float* __restrict__ h)
{
    int n = blockIdx.x;
    int f = threadIdx.x;
    int o0 = g_off[n*4+0], o1 = g_off[n*4+1], o2 = g_off[n*4+2];
    int o3 = g_off[n*4+3], o4 = g_off[n*4+4];

    float a0 = 0.f, a1 = 0.f, a2 = 0.f, a3 = 0.f;
    #pragma unroll 4
    for (int i = o0; i < o4; ++i) {
        float v = __ldg(&h[(size_t)__ldg(&g_csr[i]) * HH + f]);
        if      (i < o1) a0 += v;
        else if (i < o2) a1 += v;
        else if (i < o3) a2 += v;
        else             a3 += v;
    }
    size_t base = (size_t)n * K4 + f;
    g_S[base      ] = to_tf32(a0);
    g_S[base + 128] = to_tf32(a1);
    g_S[base + 256] = to_tf32(a2);
    g_S[base + 384] = to_tf32(a3);
}

// ---------------------------------------------------------------------------
// Pipelined GEMM engine: 128x128 tile, BK=16, 3 stages, cp.async, swizzled smem
// ---------------------------------------------------------------------------
__device__ __forceinline__ uint32_t swoff(int r, int g)   // byte offset in stage
{
    return (uint32_t)((r * 16 + 4 * (g ^ ((r >> 1) & 3))) * 4);
}

struct Frag {
    uint32_t aoff[2][2];   // [mi][kq]
    uint32_t boff[4][2];   // [p][kq]
    int wm, wn, gr, gc;
};

__device__ __forceinline__ Frag make_frag(int tid)
{
    Frag f;
    int lane = tid & 31, warp = tid >> 5;
    f.wm = warp & 3;  f.wn = warp >> 2;
    f.gr = lane >> 2; f.gc = lane & 3;
    int arl = (lane & 7) + ((lane >> 3) & 1) * 8;
    int ga  = lane >> 4;
    int brl = ((lane >> 4) & 1) * 8 + (lane & 7);
    int gb  = (lane >> 3) & 1;
    #pragma unroll
    for (int mi = 0; mi < 2; ++mi)
        #pragma unroll
        for (int kq = 0; kq < 2; ++kq)
            f.aoff[mi][kq] = swoff(f.wm * 32 + mi * 16 + arl, ga + 2 * kq);
    #pragma unroll
    for (int p = 0; p < 4; ++p)
        #pragma unroll
        for (int kq = 0; kq < 2; ++kq)
            f.boff[p][kq] = swoff(f.wn * 64 + p * 16 + brl, gb + 2 * kq);
    return f;
}

__device__ __forceinline__ void mma_stage(float acc[2][8][4],
                                          uint32_t aS, uint32_t bS, const Frag& fg)
{
    #pragma unroll
    for (int kq = 0; kq < 2; ++kq) {
        uint32_t a0[4], a1[4];
        ldsm_x4(a0, aS + fg.aoff[0][kq]);
        ldsm_x4(a1, aS + fg.aoff[1][kq]);
        #pragma unroll
        for (int p = 0; p < 4; ++p) {
            uint32_t b4[4];
            ldsm_x4(b4, bS + fg.boff[p][kq]);
            mma_tf32(acc[0][2*p],     a0, b4);
            mma_tf32(acc[0][2*p + 1], a0, b4 + 2);
            mma_tf32(acc[1][2*p],     a1, b4);
            mma_tf32(acc[1][2*p + 1], a1, b4 + 2);
        }
    }
}

// Issue one 16-K tile (A: 128 rows, guarded; B: 128 weight rows) via cp.async
__device__ __forceinline__ void pipe_issue(uint32_t aS, uint32_t bS,
                                           const float* A0, const float* A1, int lda0,
                                           const float* W, int wld,
                                           int row0, int kt, int tid)
{
    const bool   a1   = (A1 != nullptr) && (kt >= 128);
    const float* Ap   = a1 ? A1 : A0;
    const int    lda  = a1 ? 128 : lda0;
    const int    kc   = a1 ? (kt - 128) : kt;
    #pragma unroll
    for (int i = 0; i < 2; ++i) {
        int slot = tid + i * 256;
        int r = slot >> 2, g = slot & 3;
        uint32_t so = swoff(r, g);
        int rowA = row0 + r;
        int sz = (rowA < NN) ? 16 : 0;
        if (rowA >= NN) rowA = NN - 1;
        const float* sa = Ap + (size_t)rowA * lda + kc + g * 4;
        asm volatile("cp.async.cg.shared.global [%0], [%1], 16, %2;\n"
                     :: "r"(aS + so), "l"(sa), "r"(sz) : "memory");
        const float* sw = W + (size_t)r * wld + kt + g * 4;
        asm volatile("cp.async.cg.shared.global [%0], [%1], 16;\n"
                     :: "r"(bS + so), "l"(sw) : "memory");
    }
}

// Full pipelined mainloop. Stage size = 2048 floats (8192 bytes).
__device__ __forceinline__ void pipe_core(float acc[2][8][4],
                                          uint32_t aB, uint32_t bB,
                                          const float* A0, const float* A1, int lda0,
                                          int K, const float* W, int wld,
                                          int row0, const Frag& fg, int tid)
{
    #pragma unroll
    for (int mi = 0; mi < 2; ++mi)
        #pragma unroll
        for (int ni = 0; ni < 8; ++ni)
            #pragma unroll
            for (int q = 0; q < 4; ++q) acc[mi][ni][q] = 0.f;

    const int niter = K >> 4;
    pipe_issue(aB,        bB,        A0, A1, lda0, W, wld, row0, 0,  tid);
    CP_COMMIT();
    pipe_issue(aB + 8192, bB + 8192, A0, A1, lda0, W, wld, row0, 16, tid);
    CP_COMMIT();

    int st_c = 0;    // compute stage
    for (int i = 0; i < niter; ++i) {
        if (i == niter - 1) { CP_WAIT0(); } else { CP_WAIT1(); }
        __syncthreads();
        if (i + 2 < niter) {
            int st_w = (i + 2) % 3;
            pipe_issue(aB + st_w * 8192, bB + st_w * 8192,
                       A0, A1, lda0, W, wld, row0, (i + 2) * 16, tid);
            CP_COMMIT();
        }
        mma_stage(acc, aB + st_c * 8192, bB + st_c * 8192, fg);
        st_c = (st_c + 1 == 3) ? 0 : st_c + 1;
    }
}

#define PIPE_SMEM \
    __shared__ __align__(16) float As[3 * 2048]; \
    __shared__ __align__(16) float Bs[3 * 2048]; \
    const uint32_t aB = (uint32_t)__cvta_generic_to_shared(As); \
    const uint32_t bB = (uint32_t)__cvta_generic_to_shared(Bs);

// ---------------------------------------------------------------------------
// k_inc: inc[m,f] = tf32( S@Wcat + deg-bias )  (K=512)
// ---------------------------------------------------------------------------
__global__ void __launch_bounds__(256)
k_inc(const float* __restrict__ S, const float* __restrict__ Wc,
      const float* __restrict__ bl, float* __restrict__ inc)
{
    PIPE_SMEM
    const int tid  = threadIdx.x;
    const int row0 = blockIdx.x * 128;
    const Frag fg  = make_frag(tid);

    float acc[2][8][4];
    pipe_core(acc, aB, bB, S, nullptr, K4, K4, Wc, K4, row0, fg, tid);

    #pragma unroll
    for (int mi = 0; mi < 2; ++mi) {
        const int rbase = row0 + fg.wm * 32 + mi * 16 + fg.gr;
        float dg[2][4];
        #pragma unroll
        for (int hh = 0; hh < 2; ++hh) {
            int r = rbase + hh * 8;
            if (r < NN) {
                int o0 = g_off[r*4+0], o1 = g_off[r*4+1], o2 = g_off[r*4+2];
                int o3 = g_off[r*4+3], o4 = g_off[r*4+4];
                dg[hh][0] = (float)(o1 - o0); dg[hh][1] = (float)(o2 - o1);
                dg[hh][2] = (float)(o3 - o2); dg[hh][3] = (float)(o4 - o3);
            }
        }
        #pragma unroll
        for (int ni = 0; ni < 8; ++ni) {
            const int f = fg.wn * 64 + ni * 8 + fg.gc * 2;
            #pragma unroll
            for (int hh = 0; hh < 2; ++hh) {
                int r = rbase + hh * 8;
                if (r < NN) {
                    float v0 = acc[mi][ni][hh * 2 + 0];
                    float v1 = acc[mi][ni][hh * 2 + 1];
                    #pragma unroll
                    for (int t = 0; t < 4; ++t) {
                        float2 bb = *reinterpret_cast<const float2*>(bl + t * 128 + f);
                        v0 += dg[hh][t] * bb.x;
                        v1 += dg[hh][t] * bb.y;
                    }
                    *reinterpret_cast<float2*>(inc + (size_t)r * HH + f) =
                        make_float2(to_tf32(v0), to_tf32(v1));
                }
            }
        }
    }
}

// ---------------------------------------------------------------------------
// k_gates: gates[N][384] = [r | z | xn] pre-activations
// grid (391,3): y<2 -> rz half y (A=[inc|h32], K=256); y=2 -> xn (A=inc, K=128)
// ---------------------------------------------------------------------------
__global__ void __launch_bounds__(256)
k_gates(const float* __restrict__ inc, const float* __restrict__ h32,
        const float* __restrict__ Wrz, const float* __restrict__ Wxn,
        const float* __restrict__ bias,      // b0cat or null
        const float* __restrict__ Cin,       // gc1 or null
        float* __restrict__ gates)
{
    PIPE_SMEM
    const int tid  = threadIdx.x;
    const int row0 = blockIdx.x * 128;
    const int y    = blockIdx.y;
    const Frag fg  = make_frag(tid);

    float acc[2][8][4];
    if (y < 2)
        pipe_core(acc, aB, bB, inc, h32, HH, 256, Wrz + (size_t)y * 128 * 256, 256, row0, fg, tid);
    else
        pipe_core(acc, aB, bB, inc, nullptr, HH, 128, Wxn, 128, row0, fg, tid);

    const int ccol0 = y * 128;
    #pragma unroll
    for (int mi = 0; mi < 2; ++mi) {
        const int rbase = row0 + fg.wm * 32 + mi * 16 + fg.gr;
        #pragma unroll
        for (int ni = 0; ni < 8; ++ni) {
            const int cc = ccol0 + fg.wn * 64 + ni * 8 + fg.gc * 2;
            #pragma unroll
            for (int hh = 0; hh < 2; ++hh) {
                int r = rbase + hh * 8;
                if (r < NN) {
                    float v0 = acc[mi][ni][hh * 2 + 0];
                    float v1 = acc[mi][ni][hh * 2 + 1];
                    if (bias) { v0 += bias[cc]; v1 += bias[cc + 1]; }
                    if (Cin) {
                        float2 ci = *reinterpret_cast<const float2*>(Cin + (size_t)r * 384 + cc);
                        v0 += ci.x; v1 += ci.y;
                    }
                    *reinterpret_cast<float2*>(gates + (size_t)r * 384 + cc) = make_float2(v0, v1);
                }
            }
        }
    }
}

// ---------------------------------------------------------------------------
// k_pre: gc1[N][384] = x-part of layer1 gates (A=h32(x), W=W1x rows y*128)
// ---------------------------------------------------------------------------
__global__ void __launch_bounds__(256)
k_pre(const float* __restrict__ h32, const float* __restrict__ W1x,
      const float* __restrict__ bias, float* __restrict__ gc1)
{
    PIPE_SMEM
    const int tid  = threadIdx.x;
    const int row0 = blockIdx.x * 128;
    const int y    = blockIdx.y;
    const Frag fg  = make_frag(tid);

    float acc[2][8][4];
    pipe_core(acc, aB, bB, h32, nullptr, HH, 128, W1x + (size_t)y * 128 * 128, 128, row0, fg, tid);

    const int ccol0 = y * 128;
    #pragma unroll
    for (int mi = 0; mi < 2; ++mi) {
        const int rbase = row0 + fg.wm * 32 + mi * 16 + fg.gr;
        #pragma unroll
        for (int ni = 0; ni < 8; ++ni) {
            const int cc = ccol0 + fg.wn * 64 + ni * 8 + fg.gc * 2;
            #pragma unroll
            for (int hh = 0; hh < 2; ++hh) {
                int r = rbase + hh * 8;
                if (r < NN) {
                    float v0 = acc[mi][ni][hh * 2 + 0] + bias[cc];
                    float v1 = acc[mi][ni][hh * 2 + 1] + bias[cc + 1];
                    *reinterpret_cast<float2*>(gc1 + (size_t)r * 384 + cc) = make_float2(v0, v1);
                }
            }
        }
    }
}

// ---------------------------------------------------------------------------
// k_hn: hn = h32@Whn; fused GRU: h = (1-z)*tanh(xn + r*hn) + z*h; h32 = tf32(h)
// ---------------------------------------------------------------------------
__global__ void __launch_bounds__(256)
k_hn(const float* __restrict__ hin, const float* __restrict__ h32in,
     const float* __restrict__ Whn, const float* __restrict__ bhn,
     const float* __restrict__ gates,
     float* __restrict__ hout, float* __restrict__ h32out)
{
    PIPE_SMEM
    const int tid  = threadIdx.x;
    const int row0 = blockIdx.x * 128;
    const Frag fg  = make_frag(tid);

    float acc[2][8][4];
    pipe_core(acc, aB, bB, h32in, nullptr, HH, 128, Whn, 128, row0, fg, tid);

    #pragma unroll
    for (int mi = 0; mi < 2; ++mi) {
        const int rbase = row0 + fg.wm * 32 + mi * 16 + fg.gr;
        #pragma unroll
        for (int ni = 0; ni < 8; ++ni) {
            const int cc = fg.wn * 64 + ni * 8 + fg.gc * 2;
            #pragma unroll
            for (int hh = 0; hh < 2; ++hh) {
                int r = rbase + hh * 8;
                if (r < NN) {
                    float hn0 = acc[mi][ni][hh * 2 + 0] + bhn[cc];
                    float hn1 = acc[mi][ni][hh * 2 + 1] + bhn[cc + 1];
                    const float* g = gates + (size_t)r * 384;
                    float2 rv = *reinterpret_cast<const float2*>(g + cc);
                    float2 zv = *reinterpret_cast<const float2*>(g + 128 + cc);
                    float2 xn = *reinterpret_cast<const float2*>(g + 256 + cc);
                    float2 hv = *reinterpret_cast<const float2*>(hin + (size_t)r * HH + cc);
                    float r0 = 1.0f / (1.0f + expf(-rv.x));
                    float r1 = 1.0f / (1.0f + expf(-rv.y));
                    float z0 = 1.0f / (1.0f + expf(-zv.x));
                    float z1 = 1.0f / (1.0f + expf(-zv.y));
                    float n0 = tanhf(xn.x + r0 * hn0);
                    float n1 = tanhf(xn.y + r1 * hn1);
                    float o0 = (1.0f - z0) * n0 + z0 * hv.x;
                    float o1 = (1.0f - z1) * n1 + z1 * hv.y;
                    *reinterpret_cast<float2*>(hout + (size_t)r * HH + cc) = make_float2(o0, o1);
                    *reinterpret_cast<float2*>(h32out + (size_t)r * HH + cc) =
                        make_float2(to_tf32(o0), to_tf32(o1));
                }
            }
        }
    }
}

// ---------------------------------------------------------------------------
// Launch. Order chosen so the ncu capture slot (5th counted launch) = agg.
// ---------------------------------------------------------------------------
extern "C" void kernel_launch(void* const* d_in, const int* in_sizes, int n_in,
                              void* d_out, int out_size)
{
    const float* x        = (const float*)d_in[0];
    const int*   edges    = (const int*)  d_in[1];
    const float* msg_W    = (const float*)d_in[2];
    const float* msg_b    = (const float*)d_in[3];
    const float* g0_Wih   = (const float*)d_in[4];
    const float* g0_Whh   = (const float*)d_in[5];
    const float* g0_bih   = (const float*)d_in[6];
    const float* g0_bhh   = (const float*)d_in[7];
    const float* g1_Wih   = (const float*)d_in[8];
    const float* g1_Whh   = (const float*)d_in[9];
    const float* g1_bih   = (const float*)d_in[10];
    const float* g1_bhh   = (const float*)d_in[11];

    float *h_, *h32_, *S_, *inc_, *gates_, *gc1_, *Wcat_, *Wrz0_, *Wrz1_;
    float *W1x_, *Wxn0_, *Wxn1_, *Whn0_, *Whn1_, *b0cat_, *b1cat_;
    int *off_, *cur_;
    cudaGetSymbolAddress((void**)&h_,     g_h);
    cudaGetSymbolAddress((void**)&h32_,   g_h32);
    cudaGetSymbolAddress((void**)&S_,     g_S);
    cudaGetSymbolAddress((void**)&inc_,   g_inc);
    cudaGetSymbolAddress((void**)&gates_, g_gates);
    cudaGetSymbolAddress((void**)&gc1_,   g_gc1);
    cudaGetSymbolAddress((void**)&Wcat_,  g_Wcat);
    cudaGetSymbolAddress((void**)&Wrz0_,  g_Wrz0);
    cudaGetSymbolAddress((void**)&Wrz1_,  g_Wrz1);
    cudaGetSymbolAddress((void**)&W1x_,   g_W1x);
    cudaGetSymbolAddress((void**)&Wxn0_,  g_Wxn0);
    cudaGetSymbolAddress((void**)&Wxn1_,  g_Wxn1);
    cudaGetSymbolAddress((void**)&Whn0_,  g_Whn0);
    cudaGetSymbolAddress((void**)&Whn1_,  g_Whn1);
    cudaGetSymbolAddress((void**)&b0cat_, g_b0cat);
    cudaGetSymbolAddress((void**)&b1cat_, g_b1cat);
    cudaGetSymbolAddress((void**)&off_,   g_off);
    cudaGetSymbolAddress((void**)&cur_,   g_cur);

    const size_t hbytes = (size_t)NN * HH * sizeof(float);
    const int    nblk   = (NN + 127)/128;   // 391
    const dim3   g3(nblk, 3);

    cudaMemcpyAsync(h_, x, hbytes, cudaMemcpyDeviceToDevice);

    // (1) wcat + zero cnt   (2) count   (3) scan   (4) fill   (5) agg  <- ncu slot
    wcat_zero_kernel<<<(SEGS + 255)/256, 256>>>(msg_W);
    count_kernel<<<(TT*EE + 255)/256, 256>>>(edges);
    scan_kernel<<<1, 1024>>>();
    cudaMemcpyAsync(cur_, off_, SEGS * sizeof(int), cudaMemcpyDeviceToDevice);
    fill_kernel<<<(TT*EE + 255)/256, 256>>>(edges);

    // ---- step 1 (layer 0), with prep kernels interleaved after k_inc ----
    agg_kernel<<<NN, HH>>>(h_);
    k_inc<<<nblk, 256>>>(S_, Wcat_ + 0, msg_b, inc_);
    build_prep<<<(246528 + 255)/256, 256>>>(g0_Wih, g0_Whh, g0_bih, g0_bhh,
                                            g1_Wih, g1_Whh, g1_bih, g1_bhh);
    round_kernel<<<(NN*HH + 255)/256, 256>>>(x, h32_);
    k_pre<<<g3, 256>>>(h32_, W1x_, b1cat_, gc1_);
    k_gates<<<g3, 256>>>(inc_, h32_, Wrz0_, Wxn0_, b0cat_, nullptr, gates_);
    k_hn<<<nblk, 256>>>(h_, h32_, Whn0_, g0_bhh + 256, gates_, h_, h32_);

    for (int l = 0; l < 2; ++l) {
        const float* Wc  = Wcat_ + (size_t)l * HH * K4;
        const float* bl  = msg_b + (size_t)l * TT * HH;
        const float* Wrz = l ? Wrz1_ : Wrz0_;
        const float* Wxn = l ? Wxn1_ : Wxn0_;
        const float* Whn = l ? Whn1_ : Whn0_;
        const float* bhn = (l ? g1_bhh : g0_bhh) + 256;
        const float* bias = l ? nullptr : b0cat_;
        const float* cin  = l ? gc1_ : nullptr;
        for (int s = (l ? 0 : 1); s < 3; ++s) {
            agg_kernel<<<NN, HH>>>(h_);
            k_inc<<<nblk, 256>>>(S_, Wc, bl, inc_);
            k_gates<<<g3, 256>>>(inc_, h32_, Wrz, Wxn, bias, cin, gates_);
            k_hn<<<nblk, 256>>>(h_, h32_, Whn, bhn, gates_, h_, h32_);
        }
    }

    cudaMemcpyAsync(d_out, h_, hbytes, cudaMemcpyDeviceToDevice);
}